// round 5
// baseline (speedup 1.0000x reference)
#include <cuda_runtime.h>

// Problem constants (fixed shapes for this dataset)
#define T_C 500000
#define M_C 50000
#define B_C 5000
#define D_C 256
#define K_C 100

// Scratch (alloc-free rule: __device__ globals)
__device__ float g_men_emb[(size_t)M_C * D_C];   // [M, D] mention mean embeddings
__device__ float g_sel[M_C];                     // [M] selected score per mention
__device__ int   g_wrow[M_C];                    // [M] chosen linear-weight row per mention

// ---------------------------------------------------------------------------
// Kernel 0: per-bag argmax over typeTensor row (first-max tie-break, like
// jnp.argmax), then scatter the winning row index to all mentions of the bag.
// One warp per bag.
// ---------------------------------------------------------------------------
__global__ void bag_argmax_kernel(const float* __restrict__ typeT,
                                  const int* __restrict__ scope,
                                  int B, int K) {
    int b = blockIdx.x;
    if (b >= B) return;
    int lane = threadIdx.x;

    float best = -INFINITY;
    int bidx = K;  // sentinel larger than any real idx
    for (int k = lane; k < K; k += 32) {
        float v = typeT[(size_t)b * K + k];
        if (v > best) { best = v; bidx = k; }  // strided walk is ascending -> first max kept
    }
    // warp reduce: max value, smaller index on tie
    for (int off = 16; off; off >>= 1) {
        float ov = __shfl_down_sync(0xffffffffu, best, off);
        int   oi = __shfl_down_sync(0xffffffffu, bidx, off);
        if (ov > best || (ov == best && oi < bidx)) { best = ov; bidx = oi; }
    }
    bidx = __shfl_sync(0xffffffffu, bidx, 0);

    int s0 = scope[b], s1 = scope[b + 1];
    for (int m = s0 + lane; m < s1; m += 32) g_wrow[m] = bidx;
}

// ---------------------------------------------------------------------------
// Kernel 1 (dominant): one block (256 threads = D) per mention.
//   men_emb[m,d] = mean over tokens of word_embedding[feature[t], d]
//   sel[m]      = men_emb[m,:] . W[wrow[m],:]
// Token rows are 1KB contiguous -> fully coalesced.
// ---------------------------------------------------------------------------
__global__ void mention_kernel(const int* __restrict__ feat,
                               const int* __restrict__ off,
                               const float* __restrict__ Wemb,
                               const float* __restrict__ Wlin,
                               int T, int M) {
    int m = blockIdx.x;
    if (m >= M) return;
    int d = threadIdx.x;  // 0..255

    int start = off[m];
    int end   = (m + 1 < M) ? off[m + 1] : T;

    float acc = 0.0f;
    int t = start;
    // unroll-by-2 with independent feature prefetch to expose MLP
    for (; t + 1 < end; t += 2) {
        int v0 = __ldg(&feat[t]);
        int v1 = __ldg(&feat[t + 1]);
        float e0 = __ldg(&Wemb[(size_t)v0 * D_C + d]);
        float e1 = __ldg(&Wemb[(size_t)v1 * D_C + d]);
        acc += e0;
        acc += e1;
    }
    if (t < end) {
        int v0 = __ldg(&feat[t]);
        acc += __ldg(&Wemb[(size_t)v0 * D_C + d]);
    }

    float mean = acc / (float)(end - start);
    g_men_emb[(size_t)m * D_C + d] = mean;

    int wr = g_wrow[m];
    float p = mean * __ldg(&Wlin[(size_t)wr * D_C + d]);

    // block-reduce sum over 256 threads
    __shared__ float s_warp[8];
    for (int o = 16; o; o >>= 1) p += __shfl_down_sync(0xffffffffu, p, o);
    if ((d & 31) == 0) s_warp[d >> 5] = p;
    __syncthreads();
    if (d < 8) {
        float v = s_warp[d];
        for (int o = 4; o; o >>= 1) v += __shfl_down_sync(0xffu, v, o);
        if (d == 0) g_sel[m] = v;
    }
}

// ---------------------------------------------------------------------------
// Kernel 2: one block (256 threads) per bag.
//   softmax over sel within bag -> att; bag_emb = sum att * men_emb;
//   out[b,k] = bag_emb . W[k,:]
// ---------------------------------------------------------------------------
__global__ void bag_kernel(const int* __restrict__ scope,
                           const float* __restrict__ Wlin,
                           int B, int K,
                           float* __restrict__ out) {
    int b = blockIdx.x;
    if (b >= B) return;
    int tid = threadIdx.x;
    int s0 = scope[b], s1 = scope[b + 1];

    __shared__ float s_red[8];
    __shared__ float s_mx, s_sum;
    __shared__ float s_bag[D_C];

    // --- segment max ---
    float mx = -INFINITY;
    for (int m = s0 + tid; m < s1; m += 256) mx = fmaxf(mx, g_sel[m]);
    for (int o = 16; o; o >>= 1) mx = fmaxf(mx, __shfl_down_sync(0xffffffffu, mx, o));
    if ((tid & 31) == 0) s_red[tid >> 5] = mx;
    __syncthreads();
    if (tid == 0) {
        float v = s_red[0];
        #pragma unroll
        for (int i = 1; i < 8; i++) v = fmaxf(v, s_red[i]);
        s_mx = v;
    }
    __syncthreads();
    float mxv = s_mx;

    // --- sum of exp ---
    float se = 0.0f;
    for (int m = s0 + tid; m < s1; m += 256) se += expf(g_sel[m] - mxv);
    for (int o = 16; o; o >>= 1) se += __shfl_down_sync(0xffffffffu, se, o);
    if ((tid & 31) == 0) s_red[tid >> 5] = se;
    __syncthreads();
    if (tid == 0) {
        float v = 0.0f;
        #pragma unroll
        for (int i = 0; i < 8; i++) v += s_red[i];
        s_sum = v;
    }
    __syncthreads();
    float inv_s = 1.0f / s_sum;

    // --- bag_emb[d] = sum_m att_m * men_emb[m,d] ---
    int d = tid;
    float acc = 0.0f;
    for (int m = s0; m < s1; m++) {
        float a = expf(g_sel[m] - mxv) * inv_s;  // broadcast load
        acc += a * g_men_emb[(size_t)m * D_C + d];
    }
    s_bag[d] = acc;
    __syncthreads();

    // --- out[b,k] = bag_emb . W[k,:]  (8 warps cover K) ---
    int warp = tid >> 5, lane = tid & 31;
    for (int k = warp; k < K; k += 8) {
        float p = 0.0f;
        #pragma unroll
        for (int i = 0; i < 8; i++) {
            int dd = lane + 32 * i;
            p += s_bag[dd] * Wlin[(size_t)k * D_C + dd];
        }
        for (int o = 16; o; o >>= 1) p += __shfl_down_sync(0xffffffffu, p, o);
        if (lane == 0) out[(size_t)b * K + k] = p;
    }
}

// ---------------------------------------------------------------------------
extern "C" void kernel_launch(void* const* d_in, const int* in_sizes, int n_in,
                              void* d_out, int out_size) {
    const int*   feat  = (const int*)d_in[0];    // feature_seq [T]
    const int*   off   = (const int*)d_in[1];    // offset_seq  [M]
    const int*   scope = (const int*)d_in[2];    // scope       [B+1]
    const float* typeT = (const float*)d_in[3];  // typeTensor  [B,K]
    const float* Wemb  = (const float*)d_in[4];  // word_embedding [V,D]
    const float* Wlin  = (const float*)d_in[5];  // linear_weight  [K,D]
    float* out = (float*)d_out;

    int T = in_sizes[0];
    int M = in_sizes[1];
    int B = in_sizes[2] - 1;
    int K = in_sizes[3] / B;

    bag_argmax_kernel<<<B, 32>>>(typeT, scope, B, K);
    mention_kernel<<<M, 256>>>(feat, off, Wemb, Wlin, T, M);
    bag_kernel<<<B, 256>>>(scope, Wlin, B, K, out);
}